// round 4
// baseline (speedup 1.0000x reference)
#include <cuda_runtime.h>

// ---------------------------------------------------------------------------
// Problem constants
// ---------------------------------------------------------------------------
#define T_  2048
#define B_  256
#define I_  64
#define H_  128
#define G4_ 512   // 4*H
#define NH_ 512
#define O_  64

// Device-global scratch (allocation-free rule)
__device__ float g_xg[(size_t)T_ * B_ * G4_];  // [T,B,4H], includes biases
__device__ float g_hs[(size_t)T_ * B_ * H_];   // [T,B,H]

// Output layout: out[T,B,O] | hT[1,B,H] | cT[1,B,H]
#define OUT_ELEMS ((size_t)T_ * B_ * O_)
#define HT_OFF    (OUT_ELEMS)
#define CT_OFF    (OUT_ELEMS + (size_t)B_ * H_)

__device__ __forceinline__ float sigf(float x)      { return 1.f / (1.f + __expf(-x)); }
__device__ __forceinline__ float tanhfast(float x)  { return 2.f / (1.f + __expf(-2.f * x)) - 1.f; }

// ---------------------------------------------------------------------------
// Kernel A: xg[row, g] = sum_i x[row,i] * W_ih[g,i] + (b_ih[g]+b_hh[g])
//   row = t*B+b flattened (524288 rows), K=64, N=512.
//   Tile 64 rows x 64 gates, 256 threads (16x16 grid, 4x4 microtile).
// ---------------------------------------------------------------------------
__global__ void __launch_bounds__(256) xg_kernel(const float* __restrict__ x,
                                                 const float* __restrict__ Wih,
                                                 const float* __restrict__ bih,
                                                 const float* __restrict__ bhh) {
    __shared__ float sX[64 * 65];   // [row][k]  pad 65
    __shared__ float sW[64 * 65];   // [k][gate] transposed, pad 65
    __shared__ float sB[64];
    const int tid = threadIdx.x;
    const int rowBase = blockIdx.x * 64;
    const int gBase = blockIdx.y * 64;

    // stage x tile (coalesced float4)
    for (int idx = tid; idx < 1024; idx += 256) {
        int r = idx >> 4, i4 = idx & 15;
        float4 v = reinterpret_cast<const float4*>(x)[(size_t)(rowBase + r) * 16 + i4];
        float* d = &sX[r * 65 + i4 * 4];
        d[0] = v.x; d[1] = v.y; d[2] = v.z; d[3] = v.w;
    }
    // stage W_ih tile transposed
    for (int idx = tid; idx < 1024; idx += 256) {
        int g = idx >> 4, k4 = idx & 15;
        float4 v = reinterpret_cast<const float4*>(Wih)[(size_t)(gBase + g) * 16 + k4];
        sW[(k4 * 4 + 0) * 65 + g] = v.x;
        sW[(k4 * 4 + 1) * 65 + g] = v.y;
        sW[(k4 * 4 + 2) * 65 + g] = v.z;
        sW[(k4 * 4 + 3) * 65 + g] = v.w;
    }
    if (tid < 64) sB[tid] = bih[gBase + tid] + bhh[gBase + tid];
    __syncthreads();

    const int tx = tid & 15, ty = tid >> 4;
    float acc[4][4];
#pragma unroll
    for (int i = 0; i < 4; i++)
#pragma unroll
        for (int j = 0; j < 4; j++) acc[i][j] = 0.f;

#pragma unroll 8
    for (int k = 0; k < 64; k++) {
        float a[4], w[4];
#pragma unroll
        for (int i = 0; i < 4; i++) a[i] = sX[(ty + 16 * i) * 65 + k];
#pragma unroll
        for (int j = 0; j < 4; j++) w[j] = sW[k * 65 + tx + 16 * j];
#pragma unroll
        for (int i = 0; i < 4; i++)
#pragma unroll
            for (int j = 0; j < 4; j++) acc[i][j] += a[i] * w[j];
    }

#pragma unroll
    for (int i = 0; i < 4; i++) {
        size_t rowOff = (size_t)(rowBase + ty + 16 * i) * G4_;
#pragma unroll
        for (int j = 0; j < 4; j++) {
            int c = tx + 16 * j;
            g_xg[rowOff + gBase + c] = acc[i][j] + sB[c];
        }
    }
}

// ---------------------------------------------------------------------------
// Kernel B: persistent LSTM scan. 128 CTAs x 256 threads, 2 batch rows/CTA.
// W_hh split: k<108 in SMEM (216 KB), k=108..127 in regs (20 per gate).
// Thread tid computes gates g0=tid, g1=tid+256, for both batch rows.
// ---------------------------------------------------------------------------
#define KS_ 108
#define KR_ 20
#define LSTM_SMEM_BYTES ((G4_ * KS_ + 2 * H_ + 8 * H_) * 4)   // 226304

__global__ void __launch_bounds__(256, 1) lstm_kernel(const float* __restrict__ Whh,
                                                      float* __restrict__ outp) {
    extern __shared__ float smem[];
    float* sW = smem;                 // [512][108] gate-major
    float* sH = sW + G4_ * KS_;       // [2][128]
    float* sG = sH + 2 * H_;          // [4 types][2 rows][128 units]

    const int tid = threadIdx.x;
    const int row0 = blockIdx.x * 2;
    const int g0 = tid, g1 = tid + 256;

    // stage W_hh k<108 (27 float4 per gate row; W_hh row stride = 32 float4)
    const float4* W4 = reinterpret_cast<const float4*>(Whh);
    float4* sW4 = reinterpret_cast<float4*>(sW);
    for (int idx = tid; idx < G4_ * 27; idx += 256) {
        int g = idx / 27, k4 = idx % 27;
        sW4[g * 27 + k4] = W4[g * 32 + k4];
    }
    // register tail weights k = 108..127
    float rw0[KR_], rw1[KR_];
#pragma unroll
    for (int j = 0; j < KR_; j++) {
        rw0[j] = Whh[g0 * H_ + KS_ + j];
        rw1[j] = Whh[g1 * H_ + KS_ + j];
    }
    sH[tid] = 0.f;   // 256 floats == 2*H
    float c = 0.f;   // cell state owned by (b_upd, u_upd)
    float h_last = 0.f;
    __syncthreads();

    const float4* w0p = sW4 + g0 * 27;
    const float4* w1p = sW4 + g1 * 27;
    const float4* h0p = reinterpret_cast<const float4*>(sH);
    const float4* h1p = reinterpret_cast<const float4*>(sH + H_);

    // prefetch xg for t=0
    {
        size_t pb = (size_t)row0 * G4_;
        // loaded below into xn regs
    }
    size_t pb0 = (size_t)row0 * G4_;
    float xn00 = g_xg[pb0 + g0], xn01 = g_xg[pb0 + G4_ + g0];
    float xn10 = g_xg[pb0 + g1], xn11 = g_xg[pb0 + G4_ + g1];

    const int b_upd = tid >> 7, u_upd = tid & 127;
    const bool isTanh = (g1 < 384);   // warp-uniform: warps 0-3

    for (int t = 0; t < T_; t++) {
        float a00 = xn00, a01 = xn01, a10 = xn10, a11 = xn11;
        if (t + 1 < T_) {  // prefetch next timestep (consumed next iteration)
            size_t nb = ((size_t)(t + 1) * B_ + row0) * G4_;
            xn00 = g_xg[nb + g0]; xn01 = g_xg[nb + G4_ + g0];
            xn10 = g_xg[nb + g1]; xn11 = g_xg[nb + G4_ + g1];
        }
#pragma unroll 9
        for (int k4 = 0; k4 < 27; k4++) {
            float4 w0 = w0p[k4], w1 = w1p[k4];
            float4 h0 = h0p[k4], h1 = h1p[k4];
            a00 += w0.x * h0.x + w0.y * h0.y + w0.z * h0.z + w0.w * h0.w;
            a01 += w0.x * h1.x + w0.y * h1.y + w0.z * h1.z + w0.w * h1.w;
            a10 += w1.x * h0.x + w1.y * h0.y + w1.z * h0.z + w1.w * h0.w;
            a11 += w1.x * h1.x + w1.y * h1.y + w1.z * h1.z + w1.w * h1.w;
        }
#pragma unroll
        for (int j4 = 0; j4 < 5; j4++) {   // register tail k = 108..127
            float4 h0 = h0p[27 + j4], h1 = h1p[27 + j4];
            a00 += rw0[4*j4]*h0.x + rw0[4*j4+1]*h0.y + rw0[4*j4+2]*h0.z + rw0[4*j4+3]*h0.w;
            a01 += rw0[4*j4]*h1.x + rw0[4*j4+1]*h1.y + rw0[4*j4+2]*h1.z + rw0[4*j4+3]*h1.w;
            a10 += rw1[4*j4]*h0.x + rw1[4*j4+1]*h0.y + rw1[4*j4+2]*h0.z + rw1[4*j4+3]*h0.w;
            a11 += rw1[4*j4]*h1.x + rw1[4*j4+1]*h1.y + rw1[4*j4+2]*h1.z + rw1[4*j4+3]*h1.w;
        }
        // activations: g0 in [0,256) -> sigmoid (i/f). g1: [256,384) tanh (g), [384,512) sigmoid (o)
        float v00 = sigf(a00), v01 = sigf(a01), v10, v11;
        if (isTanh) { v10 = tanhfast(a10); v11 = tanhfast(a11); }
        else        { v10 = sigf(a10);     v11 = sigf(a11); }
        {
            int u0 = g0 & 127, ty0 = g0 >> 7;        // ty0 in {0,1}: i,f
            sG[(ty0 * 2 + 0) * H_ + u0] = v00;
            sG[(ty0 * 2 + 1) * H_ + u0] = v01;
            int u1 = g1 & 127, ty1 = g1 >> 7;        // ty1 in {2,3}: g,o
            sG[(ty1 * 2 + 0) * H_ + u1] = v10;
            sG[(ty1 * 2 + 1) * H_ + u1] = v11;
        }
        __syncthreads();
        // cell/h update: thread (b_upd, u_upd); 256 threads == 2 rows x 128 units
        {
            float iv = sG[(0 * 2 + b_upd) * H_ + u_upd];
            float fv = sG[(1 * 2 + b_upd) * H_ + u_upd];
            float gv = sG[(2 * 2 + b_upd) * H_ + u_upd];
            float ov = sG[(3 * 2 + b_upd) * H_ + u_upd];
            c = fv * c + iv * gv;
            float h = ov * tanhfast(c);
            h_last = h;
            sH[b_upd * H_ + u_upd] = h;
            g_hs[((size_t)t * B_ + row0 + b_upd) * H_ + u_upd] = h;
        }
        __syncthreads();
    }
    // final hidden/cell
    outp[HT_OFF + (size_t)(row0 + b_upd) * H_ + u_upd] = h_last;
    outp[CT_OFF + (size_t)(row0 + b_upd) * H_ + u_upd] = c;
}

// ---------------------------------------------------------------------------
// Kernel C: fused MLP  out = relu(hs @ W1^T + b1) @ W2^T + b2
//   Block: 64 rows x all 64 outs; 8 chunks of 64 NH streamed through SMEM.
//   Out accumulator lives in registers across chunks.
// ---------------------------------------------------------------------------
#define MLP_SMEM_BYTES ((64*130 + 64*130 + 64*66 + 64*66) * 4)   // 100352

__global__ void __launch_bounds__(256) mlp_kernel(const float* __restrict__ W1,
                                                  const float* __restrict__ b1,
                                                  const float* __restrict__ W2,
                                                  const float* __restrict__ b2,
                                                  float* __restrict__ outp) {
    extern __shared__ float sm[];
    float* sHS  = sm;                 // [64][128] pad 130
    float* sW1  = sHS + 64 * 130;     // [64 nh][128] pad 130
    float* sHid = sW1 + 64 * 130;     // [64 r][64 nh] pad 66
    float* sW2  = sHid + 64 * 66;     // [64 o][64 nh] pad 66

    const int tid = threadIdx.x;
    const int rowBase = blockIdx.x * 64;
    const int tx = tid & 15, ty = tid >> 4;

    // stage hs tile [64][128]
    for (int idx = tid; idx < 2048; idx += 256) {
        int r = idx >> 5, k4 = idx & 31;
        float4 v = reinterpret_cast<const float4*>(g_hs)[(size_t)(rowBase + r) * 32 + k4];
        float* d = &sHS[r * 130 + k4 * 4];
        d[0] = v.x; d[1] = v.y; d[2] = v.z; d[3] = v.w;
    }

    float accO[4][4];
#pragma unroll
    for (int i = 0; i < 4; i++)
#pragma unroll
        for (int j = 0; j < 4; j++) accO[i][j] = 0.f;

    for (int ch = 0; ch < 8; ch++) {
        const int nBase = ch * 64;
        __syncthreads();  // protect sW1/sW2/sHid from previous chunk's readers (also covers sHS staging on ch=0)
        // stage W1 chunk [64][128]
        for (int idx = tid; idx < 2048; idx += 256) {
            int n = idx >> 5, k4 = idx & 31;
            float4 v = reinterpret_cast<const float4*>(W1)[(size_t)(nBase + n) * 32 + k4];
            float* d = &sW1[n * 130 + k4 * 4];
            d[0] = v.x; d[1] = v.y; d[2] = v.z; d[3] = v.w;
        }
        // stage W2 chunk [64 o][64 nh]
        for (int idx = tid; idx < 1024; idx += 256) {
            int o = idx >> 4, n4 = idx & 15;
            float4 v = reinterpret_cast<const float4*>(W2)[(size_t)o * 128 + (nBase >> 2) + n4];
            float* d = &sW2[o * 66 + n4 * 4];
            d[0] = v.x; d[1] = v.y; d[2] = v.z; d[3] = v.w;
        }
        float b1r[4];
#pragma unroll
        for (int j = 0; j < 4; j++) b1r[j] = b1[nBase + tx + 16 * j];
        __syncthreads();

        // GEMM1: hidden[r][n] = relu(b1 + sum_k hs[r][k]*W1[n][k])
        float acc1[4][4];
#pragma unroll
        for (int i = 0; i < 4; i++)
#pragma unroll
            for (int j = 0; j < 4; j++) acc1[i][j] = 0.f;
#pragma unroll 8
        for (int k = 0; k < 128; k++) {
            float a[4], w[4];
#pragma unroll
            for (int i = 0; i < 4; i++) a[i] = sHS[(ty + 16 * i) * 130 + k];
#pragma unroll
            for (int j = 0; j < 4; j++) w[j] = sW1[(tx + 16 * j) * 130 + k];
#pragma unroll
            for (int i = 0; i < 4; i++)
#pragma unroll
                for (int j = 0; j < 4; j++) acc1[i][j] += a[i] * w[j];
        }
#pragma unroll
        for (int i = 0; i < 4; i++)
#pragma unroll
            for (int j = 0; j < 4; j++) {
                float v = acc1[i][j] + b1r[j];
                sHid[(ty + 16 * i) * 66 + tx + 16 * j] = fmaxf(v, 0.f);
            }
        __syncthreads();

        // GEMM2: accO[r][o] += sum_n hid[r][n] * W2[o][n]
#pragma unroll 8
        for (int n = 0; n < 64; n++) {
            float a[4], w[4];
#pragma unroll
            for (int i = 0; i < 4; i++) a[i] = sHid[(ty + 16 * i) * 66 + n];
#pragma unroll
            for (int j = 0; j < 4; j++) w[j] = sW2[(tx + 16 * j) * 66 + n];
#pragma unroll
            for (int i = 0; i < 4; i++)
#pragma unroll
                for (int j = 0; j < 4; j++) accO[i][j] += a[i] * w[j];
        }
    }

    float b2r[4];
#pragma unroll
    for (int j = 0; j < 4; j++) b2r[j] = b2[tx + 16 * j];
#pragma unroll
    for (int i = 0; i < 4; i++) {
        size_t rowOff = (size_t)(rowBase + ty + 16 * i) * O_;
#pragma unroll
        for (int j = 0; j < 4; j++)
            outp[rowOff + tx + 16 * j] = accO[i][j] + b2r[j];
    }
}

// ---------------------------------------------------------------------------
// Launcher
// ---------------------------------------------------------------------------
extern "C" void kernel_launch(void* const* d_in, const int* in_sizes, int n_in,
                              void* d_out, int out_size) {
    const float* x    = (const float*)d_in[0];
    const float* Wih  = (const float*)d_in[1];
    const float* Whh  = (const float*)d_in[2];
    const float* bih  = (const float*)d_in[3];
    const float* bhh  = (const float*)d_in[4];
    const float* W1   = (const float*)d_in[5];
    const float* b1   = (const float*)d_in[6];
    const float* W2   = (const float*)d_in[7];
    const float* b2   = (const float*)d_in[8];
    float* out = (float*)d_out;

    cudaFuncSetAttribute(lstm_kernel, cudaFuncAttributeMaxDynamicSharedMemorySize, LSTM_SMEM_BYTES);
    cudaFuncSetAttribute(mlp_kernel,  cudaFuncAttributeMaxDynamicSharedMemorySize, MLP_SMEM_BYTES);

    // A: input projection for all timesteps
    xg_kernel<<<dim3((T_ * B_) / 64, G4_ / 64), 256>>>(x, Wih, bih, bhh);
    // B: recurrent scan (persistent, batch-parallel)
    lstm_kernel<<<B_ / 2, 256, LSTM_SMEM_BYTES>>>(Whh, out);
    // C: fused MLP head
    mlp_kernel<<<(T_ * B_) / 64, 256, MLP_SMEM_BYTES>>>(W1, b1, W2, b2, out);
}

// round 8
// speedup vs baseline: 1.1003x; 1.1003x over previous
#include <cuda_runtime.h>
#include <cstdint>

// ---------------------------------------------------------------------------
// Problem constants
// ---------------------------------------------------------------------------
#define T_  2048
#define B_  256
#define I_  64
#define H_  128
#define G4_ 512   // 4*H
#define NH_ 512
#define O_  64

// Device-global scratch (allocation-free rule)
__device__ float g_xg[(size_t)T_ * B_ * G4_];   // [T,B,4H]
__device__ float g_hs[(size_t)T_ * B_ * H_];    // [T,B,H]
__device__ float g_W1h[H_ * NH_];               // [k=128][nh=512] tf32 hi (transposed W1)
__device__ float g_W1l[H_ * NH_];               //                 tf32 lo
__device__ float g_W2h[NH_ * O_];               // [nh=512][o=64]  tf32 hi (transposed W2)
__device__ float g_W2l[NH_ * O_];               //                 tf32 lo

// Output layout: out[T,B,O] | hT[1,B,H] | cT[1,B,H]
#define OUT_ELEMS ((size_t)T_ * B_ * O_)
#define HT_OFF    (OUT_ELEMS)
#define CT_OFF    (OUT_ELEMS + (size_t)B_ * H_)

__device__ __forceinline__ float sigf(float x)      { return 1.f / (1.f + __expf(-x)); }
__device__ __forceinline__ float tanhfast(float x)  { return 2.f / (1.f + __expf(-2.f * x)) - 1.f; }

// ---------------------------------------------------------------------------
// tf32 helpers (mma.sync is supported on base sm_103; tcgen05 is not
// reachable because the harness emits compute_103 PTX without the 'a' suffix)
// ---------------------------------------------------------------------------
__device__ __forceinline__ void tf32_split(float a, uint32_t& hi, uint32_t& lo) {
    uint32_t h;
    asm("cvt.rna.tf32.f32 %0, %1;" : "=r"(h) : "f"(a));
    float r = a - __uint_as_float(h);
    uint32_t l;
    asm("cvt.rna.tf32.f32 %0, %1;" : "=r"(l) : "f"(r));
    hi = h; lo = l;
}

__device__ __forceinline__ void mma8(float* d, const uint32_t* a, const uint32_t* b) {
    asm volatile("mma.sync.aligned.m16n8k8.row.col.f32.tf32.tf32.f32 "
                 "{%0,%1,%2,%3}, {%4,%5,%6,%7}, {%8,%9}, {%0,%1,%2,%3};"
                 : "+f"(d[0]), "+f"(d[1]), "+f"(d[2]), "+f"(d[3])
                 : "r"(a[0]), "r"(a[1]), "r"(a[2]), "r"(a[3]), "r"(b[0]), "r"(b[1]));
}

// ---------------------------------------------------------------------------
// Kernel P: pre-split W1/W2 into tf32 hi/lo planes (transposed for col-major B)
// ---------------------------------------------------------------------------
__global__ void prep_kernel(const float* __restrict__ W1, const float* __restrict__ W2) {
    int i0 = blockIdx.x * blockDim.x + threadIdx.x;
    int st = gridDim.x * blockDim.x;
    for (int i = i0; i < NH_ * H_; i += st) {        // W1 [nh][k] -> [k][nh]
        int nh = i >> 7, k = i & 127;
        uint32_t h, l;
        tf32_split(W1[i], h, l);
        g_W1h[k * NH_ + nh] = __uint_as_float(h);
        g_W1l[k * NH_ + nh] = __uint_as_float(l);
    }
    for (int i = i0; i < O_ * NH_; i += st) {        // W2 [o][nh] -> [nh][o]
        int o = i >> 9, nh = i & 511;
        uint32_t h, l;
        tf32_split(W2[i], h, l);
        g_W2h[nh * O_ + o] = __uint_as_float(h);
        g_W2l[nh * O_ + o] = __uint_as_float(l);
    }
}

// ---------------------------------------------------------------------------
// Kernel A: xg[row, g] = sum_i x[row,i] * W_ih[g,i] + (b_ih[g]+b_hh[g])
// ---------------------------------------------------------------------------
__global__ void __launch_bounds__(256) xg_kernel(const float* __restrict__ x,
                                                 const float* __restrict__ Wih,
                                                 const float* __restrict__ bih,
                                                 const float* __restrict__ bhh) {
    __shared__ float sX[64 * 65];
    __shared__ float sW[64 * 65];
    __shared__ float sB[64];
    const int tid = threadIdx.x;
    const int rowBase = blockIdx.x * 64;
    const int gBase = blockIdx.y * 64;

    for (int idx = tid; idx < 1024; idx += 256) {
        int r = idx >> 4, i4 = idx & 15;
        float4 v = reinterpret_cast<const float4*>(x)[(size_t)(rowBase + r) * 16 + i4];
        float* d = &sX[r * 65 + i4 * 4];
        d[0] = v.x; d[1] = v.y; d[2] = v.z; d[3] = v.w;
    }
    for (int idx = tid; idx < 1024; idx += 256) {
        int g = idx >> 4, k4 = idx & 15;
        float4 v = reinterpret_cast<const float4*>(Wih)[(size_t)(gBase + g) * 16 + k4];
        sW[(k4 * 4 + 0) * 65 + g] = v.x;
        sW[(k4 * 4 + 1) * 65 + g] = v.y;
        sW[(k4 * 4 + 2) * 65 + g] = v.z;
        sW[(k4 * 4 + 3) * 65 + g] = v.w;
    }
    if (tid < 64) sB[tid] = bih[gBase + tid] + bhh[gBase + tid];
    __syncthreads();

    const int tx = tid & 15, ty = tid >> 4;
    float acc[4][4];
#pragma unroll
    for (int i = 0; i < 4; i++)
#pragma unroll
        for (int j = 0; j < 4; j++) acc[i][j] = 0.f;

#pragma unroll 8
    for (int k = 0; k < 64; k++) {
        float a[4], w[4];
#pragma unroll
        for (int i = 0; i < 4; i++) a[i] = sX[(ty + 16 * i) * 65 + k];
#pragma unroll
        for (int j = 0; j < 4; j++) w[j] = sW[k * 65 + tx + 16 * j];
#pragma unroll
        for (int i = 0; i < 4; i++)
#pragma unroll
            for (int j = 0; j < 4; j++) acc[i][j] += a[i] * w[j];
    }

#pragma unroll
    for (int i = 0; i < 4; i++) {
        size_t rowOff = (size_t)(rowBase + ty + 16 * i) * G4_;
#pragma unroll
        for (int j = 0; j < 4; j++) {
            int c = tx + 16 * j;
            g_xg[rowOff + gBase + c] = acc[i][j] + sB[c];
        }
    }
}

// ---------------------------------------------------------------------------
// Kernel B: persistent LSTM scan (R4 version: fp32 g_hs output)
// ---------------------------------------------------------------------------
#define KS_ 108
#define KR_ 20
#define LSTM_SMEM_BYTES ((G4_ * KS_ + 2 * H_ + 8 * H_) * 4)   // 226304

__global__ void __launch_bounds__(256, 1) lstm_kernel(const float* __restrict__ Whh,
                                                      float* __restrict__ outp) {
    extern __shared__ float smem[];
    float* sW = smem;
    float* sH = sW + G4_ * KS_;
    float* sG = sH + 2 * H_;

    const int tid = threadIdx.x;
    const int row0 = blockIdx.x * 2;
    const int g0 = tid, g1 = tid + 256;

    const float4* W4 = reinterpret_cast<const float4*>(Whh);
    float4* sW4 = reinterpret_cast<float4*>(sW);
    for (int idx = tid; idx < G4_ * 27; idx += 256) {
        int g = idx / 27, k4 = idx % 27;
        sW4[g * 27 + k4] = W4[g * 32 + k4];
    }
    float rw0[KR_], rw1[KR_];
#pragma unroll
    for (int j = 0; j < KR_; j++) {
        rw0[j] = Whh[g0 * H_ + KS_ + j];
        rw1[j] = Whh[g1 * H_ + KS_ + j];
    }
    sH[tid] = 0.f;
    float c = 0.f;
    float h_last = 0.f;
    __syncthreads();

    const float4* w0p = sW4 + g0 * 27;
    const float4* w1p = sW4 + g1 * 27;
    const float4* h0p = reinterpret_cast<const float4*>(sH);
    const float4* h1p = reinterpret_cast<const float4*>(sH + H_);

    size_t pb0 = (size_t)row0 * G4_;
    float xn00 = g_xg[pb0 + g0], xn01 = g_xg[pb0 + G4_ + g0];
    float xn10 = g_xg[pb0 + g1], xn11 = g_xg[pb0 + G4_ + g1];

    const int b_upd = tid >> 7, u_upd = tid & 127;
    const bool isTanh = (g1 < 384);

    for (int t = 0; t < T_; t++) {
        float a00 = xn00, a01 = xn01, a10 = xn10, a11 = xn11;
        if (t + 1 < T_) {
            size_t nb = ((size_t)(t + 1) * B_ + row0) * G4_;
            xn00 = g_xg[nb + g0]; xn01 = g_xg[nb + G4_ + g0];
            xn10 = g_xg[nb + g1]; xn11 = g_xg[nb + G4_ + g1];
        }
#pragma unroll 9
        for (int k4 = 0; k4 < 27; k4++) {
            float4 w0 = w0p[k4], w1 = w1p[k4];
            float4 h0 = h0p[k4], h1 = h1p[k4];
            a00 += w0.x * h0.x + w0.y * h0.y + w0.z * h0.z + w0.w * h0.w;
            a01 += w0.x * h1.x + w0.y * h1.y + w0.z * h1.z + w0.w * h1.w;
            a10 += w1.x * h0.x + w1.y * h0.y + w1.z * h0.z + w1.w * h0.w;
            a11 += w1.x * h1.x + w1.y * h1.y + w1.z * h1.z + w1.w * h1.w;
        }
#pragma unroll
        for (int j4 = 0; j4 < 5; j4++) {
            float4 h0 = h0p[27 + j4], h1 = h1p[27 + j4];
            a00 += rw0[4*j4]*h0.x + rw0[4*j4+1]*h0.y + rw0[4*j4+2]*h0.z + rw0[4*j4+3]*h0.w;
            a01 += rw0[4*j4]*h1.x + rw0[4*j4+1]*h1.y + rw0[4*j4+2]*h1.z + rw0[4*j4+3]*h1.w;
            a10 += rw1[4*j4]*h0.x + rw1[4*j4+1]*h0.y + rw1[4*j4+2]*h0.z + rw1[4*j4+3]*h0.w;
            a11 += rw1[4*j4]*h1.x + rw1[4*j4+1]*h1.y + rw1[4*j4+2]*h1.z + rw1[4*j4+3]*h1.w;
        }
        float v00 = sigf(a00), v01 = sigf(a01), v10, v11;
        if (isTanh) { v10 = tanhfast(a10); v11 = tanhfast(a11); }
        else        { v10 = sigf(a10);     v11 = sigf(a11); }
        {
            int u0 = g0 & 127, ty0 = g0 >> 7;
            sG[(ty0 * 2 + 0) * H_ + u0] = v00;
            sG[(ty0 * 2 + 1) * H_ + u0] = v01;
            int u1 = g1 & 127, ty1 = g1 >> 7;
            sG[(ty1 * 2 + 0) * H_ + u1] = v10;
            sG[(ty1 * 2 + 1) * H_ + u1] = v11;
        }
        __syncthreads();
        {
            float iv = sG[(0 * 2 + b_upd) * H_ + u_upd];
            float fv = sG[(1 * 2 + b_upd) * H_ + u_upd];
            float gv = sG[(2 * 2 + b_upd) * H_ + u_upd];
            float ov = sG[(3 * 2 + b_upd) * H_ + u_upd];
            c = fv * c + iv * gv;
            float h = ov * tanhfast(c);
            h_last = h;
            sH[b_upd * H_ + u_upd] = h;
            g_hs[((size_t)t * B_ + row0 + b_upd) * H_ + u_upd] = h;
        }
        __syncthreads();
    }
    outp[HT_OFF + (size_t)(row0 + b_upd) * H_ + u_upd] = h_last;
    outp[CT_OFF + (size_t)(row0 + b_upd) * H_ + u_upd] = c;
}

// ---------------------------------------------------------------------------
// Kernel C: mma.sync 3xTF32 fused MLP  out = relu(hs@W1^T + b1)@W2^T + b2
// CTA: 128 rows, 256 threads = 8 warps.  Warp w: mg=w&3 -> rows [32mg,32mg+32),
// nh2=w>>2 -> cols [32nh2, +32) of the current 64-wide NH chunk (4 n8-tiles).
// NH in 8 chunks of 64; GEMM2 accumulates across chunks in registers.
// SMEM strides chosen conflict-free: A 132 (=4 mod 32), B 72 (=8 mod 32),
// hidden 68 (=4 mod 32).
// ---------------------------------------------------------------------------
#define SA_    0                         // float offsets into dynamic smem
#define SB1H_  (SA_   + 128 * 132)       // 16896
#define SB1L_  (SB1H_ + 128 * 72)        // 26112
#define SHID_  (SB1L_ + 128 * 72)        // 35328
#define SW2H_  (SHID_ + 128 * 68)        // 44032
#define SW2L_  (SW2H_ +  64 * 72)        // 48640
#define SB1V_  (SW2L_ +  64 * 72)        // 53248
#define SB2V_  (SB1V_ + 512)             // 53760
#define MLP_SMEM_FLOATS (SB2V_ + 64)     // 53824
#define MLP_SMEM_BYTES  (MLP_SMEM_FLOATS * 4)   // 215296

__global__ void __launch_bounds__(256, 1) mlp_mma_kernel(const float* __restrict__ b1,
                                                         const float* __restrict__ b2,
                                                         float* __restrict__ outp) {
    extern __shared__ float sm[];
    const int tid = threadIdx.x;
    const int lane = tid & 31;
    const int w = tid >> 5;
    const int mg = w & 3;          // row group (32 rows)
    const int nh2 = w >> 2;        // col half (32 cols of 64-chunk)
    const size_t rowBase = (size_t)blockIdx.x * 128;

    const int rA = mg * 32 + (lane >> 2);  // A-frag row (first of 4)
    const int kA = lane & 3;               // A-frag k within k-step
    const int cB = lane >> 2;              // B-frag col within n-tile
    const int kB = lane & 3;               // B-frag k within k-step

    // stage hs tile [128][128] -> sA stride 132
    for (int i = tid; i < 4096; i += 256) {
        int r = i >> 5, c4 = i & 31;
        float4 v = reinterpret_cast<const float4*>(g_hs)[(rowBase + r) * 32 + c4];
        *reinterpret_cast<float4*>(&sm[SA_ + r * 132 + c4 * 4]) = v;
    }
    for (int i = tid; i < NH_; i += 256) sm[SB1V_ + i] = b1[i];
    if (tid < O_) sm[SB2V_ + tid] = b2[tid];

    float accO[2][4][4];
#pragma unroll
    for (int mf = 0; mf < 2; mf++)
#pragma unroll
        for (int nt = 0; nt < 4; nt++)
#pragma unroll
            for (int q = 0; q < 4; q++) accO[mf][nt][q] = 0.f;

    for (int c = 0; c < 8; c++) {
        __syncthreads();   // frees sB1/sW2/sHid from previous chunk (and covers sA staging)
        // stage W1 chunk [128k][64n] hi/lo
        for (int i = tid; i < 2048; i += 256) {
            int k = i >> 4, n4 = i & 15;
            *reinterpret_cast<float4*>(&sm[SB1H_ + k * 72 + n4 * 4]) =
                reinterpret_cast<const float4*>(g_W1h)[(k * NH_ + c * 64) / 4 + n4];
            *reinterpret_cast<float4*>(&sm[SB1L_ + k * 72 + n4 * 4]) =
                reinterpret_cast<const float4*>(g_W1l)[(k * NH_ + c * 64) / 4 + n4];
        }
        // stage W2 chunk [64k][64o] hi/lo
        for (int i = tid; i < 1024; i += 256) {
            int k = i >> 4, n4 = i & 15;
            *reinterpret_cast<float4*>(&sm[SW2H_ + k * 72 + n4 * 4]) =
                reinterpret_cast<const float4*>(g_W2h)[((c * 64 + k) * O_) / 4 + n4];
            *reinterpret_cast<float4*>(&sm[SW2L_ + k * 72 + n4 * 4]) =
                reinterpret_cast<const float4*>(g_W2l)[((c * 64 + k) * O_) / 4 + n4];
        }
        __syncthreads();

        // ---- GEMM1: hidden_chunk = hs @ W1_chunk^T  (M=128, N=64, K=128) ----
        float acc[2][4][4];
#pragma unroll
        for (int mf = 0; mf < 2; mf++)
#pragma unroll
            for (int nt = 0; nt < 4; nt++)
#pragma unroll
                for (int q = 0; q < 4; q++) acc[mf][nt][q] = 0.f;

#pragma unroll 2
        for (int ks = 0; ks < 16; ks++) {
            uint32_t Ah[2][4], Al[2][4];
#pragma unroll
            for (int mf = 0; mf < 2; mf++) {
                int r = rA + mf * 16;
                int k = ks * 8 + kA;
                float a0 = sm[SA_ + r * 132 + k];
                float a1 = sm[SA_ + (r + 8) * 132 + k];
                float a2 = sm[SA_ + r * 132 + k + 4];
                float a3 = sm[SA_ + (r + 8) * 132 + k + 4];
                tf32_split(a0, Ah[mf][0], Al[mf][0]);
                tf32_split(a1, Ah[mf][1], Al[mf][1]);
                tf32_split(a2, Ah[mf][2], Al[mf][2]);
                tf32_split(a3, Ah[mf][3], Al[mf][3]);
            }
#pragma unroll
            for (int nt = 0; nt < 4; nt++) {
                int n = nh2 * 32 + nt * 8 + cB;
                int k = ks * 8 + kB;
                uint32_t Bh[2], Bl[2];
                Bh[0] = __float_as_uint(sm[SB1H_ + k * 72 + n]);
                Bh[1] = __float_as_uint(sm[SB1H_ + (k + 4) * 72 + n]);
                Bl[0] = __float_as_uint(sm[SB1L_ + k * 72 + n]);
                Bl[1] = __float_as_uint(sm[SB1L_ + (k + 4) * 72 + n]);
#pragma unroll
                for (int mf = 0; mf < 2; mf++) {
                    mma8(acc[mf][nt], Ah[mf], Bh);
                    mma8(acc[mf][nt], Ah[mf], Bl);
                    mma8(acc[mf][nt], Al[mf], Bh);
                }
            }
        }

        // epilogue: +b1, relu -> sHid (each warp writes only its own 32x32 block)
#pragma unroll
        for (int mf = 0; mf < 2; mf++)
#pragma unroll
            for (int nt = 0; nt < 4; nt++) {
                int r = rA + mf * 16;
                int col = nh2 * 32 + nt * 8 + (lane & 3) * 2;
                float bb0 = sm[SB1V_ + c * 64 + col];
                float bb1 = sm[SB1V_ + c * 64 + col + 1];
                float2 v0, v1;
                v0.x = fmaxf(acc[mf][nt][0] + bb0, 0.f);
                v0.y = fmaxf(acc[mf][nt][1] + bb1, 0.f);
                v1.x = fmaxf(acc[mf][nt][2] + bb0, 0.f);
                v1.y = fmaxf(acc[mf][nt][3] + bb1, 0.f);
                *reinterpret_cast<float2*>(&sm[SHID_ + r * 68 + col]) = v0;
                *reinterpret_cast<float2*>(&sm[SHID_ + (r + 8) * 68 + col]) = v1;
            }
        __syncthreads();

        // ---- GEMM2: accO += hidden_chunk @ W2_chunk^T  (M=128, N=64, K=64) ----
#pragma unroll 2
        for (int ks = 0; ks < 8; ks++) {
            uint32_t Ah[2][4], Al[2][4];
#pragma unroll
            for (int mf = 0; mf < 2; mf++) {
                int r = rA + mf * 16;
                int k = ks * 8 + kA;
                float a0 = sm[SHID_ + r * 68 + k];
                float a1 = sm[SHID_ + (r + 8) * 68 + k];
                float a2 = sm[SHID_ + r * 68 + k + 4];
                float a3 = sm[SHID_ + (r + 8) * 68 + k + 4];
                tf32_split(a0, Ah[mf][0], Al[mf][0]);
                tf32_split(a1, Ah[mf][1], Al[mf][1]);
                tf32_split(a2, Ah[mf][2], Al[mf][2]);
                tf32_split(a3, Ah[mf][3], Al[mf][3]);
            }
#pragma unroll
            for (int nt = 0; nt < 4; nt++) {
                int n = nh2 * 32 + nt * 8 + cB;
                int k = ks * 8 + kB;
                uint32_t Bh[2], Bl[2];
                Bh[0] = __float_as_uint(sm[SW2H_ + k * 72 + n]);
                Bh[1] = __float_as_uint(sm[SW2H_ + (k + 4) * 72 + n]);
                Bl[0] = __float_as_uint(sm[SW2L_ + k * 72 + n]);
                Bl[1] = __float_as_uint(sm[SW2L_ + (k + 4) * 72 + n]);
#pragma unroll
                for (int mf = 0; mf < 2; mf++) {
                    mma8(accO[mf][nt], Ah[mf], Bh);
                    mma8(accO[mf][nt], Ah[mf], Bl);
                    mma8(accO[mf][nt], Al[mf], Bh);
                }
            }
        }
    }

    // output: +b2, store (8-byte stores; col even)
#pragma unroll
    for (int mf = 0; mf < 2; mf++) {
        size_t r0 = rowBase + rA + mf * 16;
#pragma unroll
        for (int nt = 0; nt < 4; nt++) {
            int col = nh2 * 32 + nt * 8 + (lane & 3) * 2;
            float bo0 = sm[SB2V_ + col];
            float bo1 = sm[SB2V_ + col + 1];
            float2 v0, v1;
            v0.x = accO[mf][nt][0] + bo0;
            v0.y = accO[mf][nt][1] + bo1;
            v1.x = accO[mf][nt][2] + bo0;
            v1.y = accO[mf][nt][3] + bo1;
            *reinterpret_cast<float2*>(outp + r0 * O_ + col) = v0;
            *reinterpret_cast<float2*>(outp + (r0 + 8) * O_ + col) = v1;
        }
    }
}

// ---------------------------------------------------------------------------
// Launcher
// ---------------------------------------------------------------------------
extern "C" void kernel_launch(void* const* d_in, const int* in_sizes, int n_in,
                              void* d_out, int out_size) {
    const float* x    = (const float*)d_in[0];
    const float* Wih  = (const float*)d_in[1];
    const float* Whh  = (const float*)d_in[2];
    const float* bih  = (const float*)d_in[3];
    const float* bhh  = (const float*)d_in[4];
    const float* W1   = (const float*)d_in[5];
    const float* b1   = (const float*)d_in[6];
    const float* W2   = (const float*)d_in[7];
    const float* b2   = (const float*)d_in[8];
    float* out = (float*)d_out;

    cudaFuncSetAttribute(lstm_kernel,    cudaFuncAttributeMaxDynamicSharedMemorySize, LSTM_SMEM_BYTES);
    cudaFuncSetAttribute(mlp_mma_kernel, cudaFuncAttributeMaxDynamicSharedMemorySize, MLP_SMEM_BYTES);

    prep_kernel<<<64, 256>>>(W1, W2);
    xg_kernel<<<dim3((T_ * B_) / 64, G4_ / 64), 256>>>(x, Wih, bih, bhh);
    lstm_kernel<<<B_ / 2, 256, LSTM_SMEM_BYTES>>>(Whh, out);
    mlp_mma_kernel<<<(T_ * B_) / 128, 256, MLP_SMEM_BYTES>>>(b1, b2, out);
}